// round 10
// baseline (speedup 1.0000x reference)
#include <cuda_runtime.h>
#include <cstdint>

// Problem constants (DescrptSeA)
#define NF      2
#define NLOC    4096
#define NALL    4608
#define NROW    (NF * NLOC)
#define NNEI    138
#define SEC1    46      // type-0 neighbors: [0,46), type-1: [46,138)
#define MDIM    100
#define AXIS    16
#define NTHREADS 320
#define GRID    296     // 2 CTAs per SM x 148 SMs

typedef unsigned long long ull;

// ---------------------------------------------------------------------------
// dtype probe: reference declares int64 indices, but JAX may emit int32.
// ---------------------------------------------------------------------------
__device__ int g_is64[2];

__global__ void probe_kernel(const unsigned* __restrict__ nlist_w,
                             const unsigned* __restrict__ atype_w) {
    if (threadIdx.x == 0 && blockIdx.x == 0) {
        int nz = 0;
        for (int p = 0; p < 512; p++) nz += (nlist_w[2 * p + 1] != 0u);
        g_is64[0] = (nz == 0) ? 1 : 0;
        nz = 0;
        for (int p = 0; p < 512; p++) nz += (atype_w[2 * p + 1] != 0u);
        g_is64[1] = (nz == 0) ? 1 : 0;
    }
}

__device__ __forceinline__ float tanh_ap(float x) {
    float y;
    asm("tanh.approx.f32 %0, %1;" : "=f"(y) : "f"(x));
    return y;
}

// ---- packed f32x2 helpers --------------------------------------------------
__device__ __forceinline__ ull pack2(float lo, float hi) {
    ull r;
    asm("mov.b64 %0, {%1, %2};" : "=l"(r) : "f"(lo), "f"(hi));
    return r;
}
__device__ __forceinline__ ull ffma2(ull a, ull b, ull c) {
    ull d;
    asm("fma.rn.f32x2 %0, %1, %2, %3;" : "=l"(d) : "l"(a), "l"(b), "l"(c));
    return d;
}
__device__ __forceinline__ ull fadd2(ull a, ull b) {
    ull d;
    asm("add.rn.f32x2 %0, %1, %2;" : "=l"(d) : "l"(a), "l"(b));
    return d;
}
__device__ __forceinline__ float hsum2(ull a) {
    float lo, hi;
    asm("mov.b64 {%0, %1}, %2;" : "=f"(lo), "=f"(hi) : "l"(a));
    return lo + hi;
}

__device__ __forceinline__ long long load_idx(const void* p, long long i, int is64) {
    if (is64) return ((const long long*)p)[i];
    return (long long)((const int*)p)[i];
}

struct SM {
    alignas(16) float env[NNEI][4];      // normalized env rows
    alignas(16) float h1[NNEI][52];      // 50 + pad (16B rows)
    alignas(16) float h0[NNEI][28];      // 25 + zero pad (16B rows)
    alignas(16) float w1T[2][50][28];    // [t][k][j], j>=25 -> 0
    alignas(16) float w0s[2][25];
    float b0s[2][25];
    alignas(16) float xyzp[6][4][MDIM];  // stage-2 partials per chunk
    alignas(16) float xyz[4][MDIM];
};

__global__ __launch_bounds__(NTHREADS, 2)
void desc_kernel(const void* __restrict__ nlist_,
                 const float* __restrict__ coord,
                 const void* __restrict__ atype_,
                 const float* __restrict__ mean,
                 const float* __restrict__ stdv,
                 const float* __restrict__ w0,
                 const float* __restrict__ b0,
                 const float* __restrict__ w1,
                 const float* __restrict__ b1,
                 const float* __restrict__ w2,
                 const float* __restrict__ b2,
                 float* __restrict__ out)
{
    extern __shared__ unsigned char smem_raw[];
    SM& sm = *reinterpret_cast<SM*>(smem_raw);

    const int tid = threadIdx.x;
    const int is64n = g_is64[0];
    const int is64a = g_is64[1];

    // ---- one-time smem staging ------------------------------------------
    for (int x = tid; x < 50; x += NTHREADS) {
        int t = x / 25, j = x % 25;
        sm.w0s[t][j] = w0[x];
        sm.b0s[t][j] = b0[x];
    }
    // w1 transposed+padded: w1T[t][k][j] = w1[t][j][k], j>=25 -> 0
    for (int x = tid; x < 2 * 50 * 28; x += NTHREADS) {
        int t = x / (50 * 28);
        int r = x - t * 50 * 28;
        int k = r / 28, j = r - k * 28;
        sm.w1T[t][k][j] = (j < 25) ? w1[t * 1250 + j * 50 + k] : 0.0f;
    }

    // ---- stage-2 roles: 6 chunks x 50 column-PAIRS (p, p+50) -------------
    // All chunks exactly 23 neighbors, type-aligned: chunks 0-1 -> type 0,
    // chunks 2-5 -> type 1. Zero trip-count divergence anywhere.
    const bool s2act = (tid < 300);
    const int tt2 = s2act ? tid : 299;    // clamp for safe addressing
    const int p   = tt2 % 50;
    const int c   = tt2 / 50;             // 0..5
    const int t2    = (c < 2) ? 0 : 1;
    const int sbeg2 = c * 23;
    const float b2A = b2[t2 * 100 + p];
    const float b2B = b2[t2 * 100 + p + 50];
    const float* wg = w2 + t2 * 5000 + p; // column base for per-row reload

    // ---- stage h1 roles: 6 segments x 50 k = 300 threads, 23 each --------
    const bool h1act = (tid < 300);
    const int kh  = tt2 % 50;
    const int seg = tt2 / 50;             // 0..5
    const int th1  = (seg < 2) ? 0 : 1;
    const int hbeg = seg * 23;
    const int hend = hbeg + 23;
    const float b1k = b1[th1 * 50 + kh];
    const int km = (kh < 25) ? kh : kh - 25;

    __syncthreads();

    // =====================  persistent row loop  ==========================
    for (int row = blockIdx.x; row < NROW; row += GRID) {
        const int f  = row >> 12;
        const int li = row & (NLOC - 1);

        // ---- stage 1: env matrix ----------------------------------------
        const long long ci = (long long)f * NALL + li;
        if (tid < NNEI) {
            const int s0 = tid;
            const float cx = coord[ci * 3 + 0];
            const float cy = coord[ci * 3 + 1];
            const float cz = coord[ci * 3 + 2];
            const int at = (int)load_idx(atype_, ci, is64a);
            long long nb = load_idx(nlist_, (long long)row * NNEI + s0, is64n);
            bool valid = (nb >= 0);
            long long j = valid ? nb : 0;
            const float* cp = coord + ((long long)f * NALL + j) * 3;
            float dx = cp[0] - cx, dy = cp[1] - cy, dz = cp[2] - cz;
            float r = sqrtf(dx * dx + dy * dy + dz * dz);
            float uu = (r - 0.5f) * (1.0f / 5.5f);
            float vv = uu * uu * uu * (uu * (-6.0f * uu + 15.0f) - 10.0f) + 1.0f;
            float w = (r < 0.5f) ? 1.0f : ((r >= 6.0f) ? 0.0f : vv);
            if (!valid) w = 0.0f;
            float inv = 1.0f / (r + 0.01f);
            float a0 = inv * w;
            float aw = inv * inv * w;
            int base = (at * NNEI + s0) * 4;
            sm.env[s0][0] = (a0      - mean[base + 0]) / stdv[base + 0];
            sm.env[s0][1] = (dx * aw - mean[base + 1]) / stdv[base + 1];
            sm.env[s0][2] = (dy * aw - mean[base + 2]) / stdv[base + 2];
            sm.env[s0][3] = (dz * aw - mean[base + 3]) / stdv[base + 3];
        }
        __syncthreads();

        // ---- stage h0: 138 x 25 (+ zero pads to 28) ---------------------
        for (int x = tid; x < NNEI * 28; x += NTHREADS) {
            int s0 = x / 28, j = x - s0 * 28;
            int t = (s0 >= SEC1);
            sm.h0[s0][j] = (j < 25)
                ? tanh_ap(sm.env[s0][0] * sm.w0s[t][j] + sm.b0s[t][j])
                : 0.0f;
        }
        __syncthreads();

        // ---- stage h1: one k per thread, wk hoisted per row -------------
        if (h1act) {
            ulonglong2 wk[7];
            const ulonglong2* w1p = (const ulonglong2*)&sm.w1T[th1][kh][0];
            #pragma unroll
            for (int v = 0; v < 7; v++) wk[v] = w1p[v];
            for (int s0 = hbeg; s0 < hend; s0++) {
                const ulonglong2* h0p = (const ulonglong2*)&sm.h0[s0][0];
                ull a0 = 0ull, a1 = 0ull;
                #pragma unroll
                for (int v = 0; v < 7; v++) {
                    ulonglong2 h = h0p[v];
                    a0 = ffma2(h.x, wk[v].x, a0);
                    a1 = ffma2(h.y, wk[v].y, a1);
                }
                float acc = hsum2(fadd2(a0, a1)) + b1k;
                sm.h1[s0][kh] = tanh_ap(acc) + sm.h0[s0][km];
            }
        }
        __syncthreads();

        // ---- stage 2: 2 columns x 2 neighbors per tile ------------------
        // 4 dot products share 2 h1-row reads and 2 register-resident w2
        // columns -> LDS:FMA ratio ~1:3.5 (vs 1:1.6 single-column).
        {
            // w2 columns p and p+50 packed over k: 50 f32x2 regs, reloaded
            // per row (not live during h1). Lane-coalesced, L1-hot.
            ull wpA[25], wpB[25];
            #pragma unroll
            for (int q = 0; q < 25; q++) {
                wpA[q] = pack2(wg[(2 * q) * 100],      wg[(2 * q + 1) * 100]);
                wpB[q] = pack2(wg[(2 * q) * 100 + 50], wg[(2 * q + 1) * 100 + 50]);
            }

            ull xA01 = 0ull, xA23 = 0ull, xB01 = 0ull, xB23 = 0ull;
            int s0 = sbeg2;
            #pragma unroll 1
            for (int it = 0; it < 11; it++, s0 += 2) {
                const ulonglong2* hpA = (const ulonglong2*)&sm.h1[s0][0];
                const ulonglong2* hpB = (const ulonglong2*)&sm.h1[s0 + 1][0];
                ull aA = 0ull, aB = 0ull, aC = 0ull, aD = 0ull;
                #pragma unroll
                for (int v = 0; v < 12; v++) {
                    ulonglong2 ha = hpA[v];
                    ulonglong2 hb = hpB[v];
                    aA = ffma2(ha.x, wpA[2 * v], aA);
                    aB = ffma2(hb.x, wpA[2 * v], aB);
                    aC = ffma2(ha.x, wpB[2 * v], aC);
                    aD = ffma2(hb.x, wpB[2 * v], aD);
                    aA = ffma2(ha.y, wpA[2 * v + 1], aA);
                    aB = ffma2(hb.y, wpA[2 * v + 1], aB);
                    aC = ffma2(ha.y, wpB[2 * v + 1], aC);
                    aD = ffma2(hb.y, wpB[2 * v + 1], aD);
                }
                ull lastA = *(const ull*)&sm.h1[s0][48];
                ull lastB = *(const ull*)&sm.h1[s0 + 1][48];
                aA = ffma2(lastA, wpA[24], aA);
                aB = ffma2(lastB, wpA[24], aB);
                aC = ffma2(lastA, wpB[24], aC);
                aD = ffma2(lastB, wpB[24], aD);
                float accAA = hsum2(aA) + b2A;   // col p,    nei s0
                float accAB = hsum2(aB) + b2A;   // col p,    nei s0+1
                float accBA = hsum2(aC) + b2B;   // col p+50, nei s0
                float accBB = hsum2(aD) + b2B;   // col p+50, nei s0+1
                float residA = sm.h1[s0][p];
                float residB = sm.h1[s0 + 1][p];
                float gAA = tanh_ap(accAA) + residA;
                float gAB = tanh_ap(accAB) + residB;
                float gBA = tanh_ap(accBA) + residA;
                float gBB = tanh_ap(accBB) + residB;
                const ull* epA = (const ull*)sm.env[s0];
                const ull* epB = (const ull*)sm.env[s0 + 1];
                ull eA01 = epA[0], eA23 = epA[1];
                ull eB01 = epB[0], eB23 = epB[1];
                xA01 = ffma2(eA01, pack2(gAA, gAA), xA01);
                xA23 = ffma2(eA23, pack2(gAA, gAA), xA23);
                xA01 = ffma2(eB01, pack2(gAB, gAB), xA01);
                xA23 = ffma2(eB23, pack2(gAB, gAB), xA23);
                xB01 = ffma2(eA01, pack2(gBA, gBA), xB01);
                xB23 = ffma2(eA23, pack2(gBA, gBA), xB23);
                xB01 = ffma2(eB01, pack2(gBB, gBB), xB01);
                xB23 = ffma2(eB23, pack2(gBB, gBB), xB23);
            }
            // tail: 23rd neighbor (uniform across all stage-2 threads)
            {
                const ulonglong2* hpA = (const ulonglong2*)&sm.h1[s0][0];
                ull aA = 0ull, aC = 0ull;
                #pragma unroll
                for (int v = 0; v < 12; v++) {
                    ulonglong2 ha = hpA[v];
                    aA = ffma2(ha.x, wpA[2 * v], aA);
                    aC = ffma2(ha.x, wpB[2 * v], aC);
                    aA = ffma2(ha.y, wpA[2 * v + 1], aA);
                    aC = ffma2(ha.y, wpB[2 * v + 1], aC);
                }
                ull lastA = *(const ull*)&sm.h1[s0][48];
                aA = ffma2(lastA, wpA[24], aA);
                aC = ffma2(lastA, wpB[24], aC);
                float accA = hsum2(aA) + b2A;
                float accB = hsum2(aC) + b2B;
                float resid = sm.h1[s0][p];
                float gA = tanh_ap(accA) + resid;
                float gB = tanh_ap(accB) + resid;
                const ull* ep = (const ull*)sm.env[s0];
                xA01 = ffma2(ep[0], pack2(gA, gA), xA01);
                xA23 = ffma2(ep[1], pack2(gA, gA), xA23);
                xB01 = ffma2(ep[0], pack2(gB, gB), xB01);
                xB23 = ffma2(ep[1], pack2(gB, gB), xB23);
            }
            if (s2act) {
                float u0, u1, u2, u3;
                asm("mov.b64 {%0, %1}, %2;" : "=f"(u0), "=f"(u1) : "l"(xA01));
                asm("mov.b64 {%0, %1}, %2;" : "=f"(u2), "=f"(u3) : "l"(xA23));
                sm.xyzp[c][0][p] = u0;
                sm.xyzp[c][1][p] = u1;
                sm.xyzp[c][2][p] = u2;
                sm.xyzp[c][3][p] = u3;
                asm("mov.b64 {%0, %1}, %2;" : "=f"(u0), "=f"(u1) : "l"(xB01));
                asm("mov.b64 {%0, %1}, %2;" : "=f"(u2), "=f"(u3) : "l"(xB23));
                sm.xyzp[c][0][p + 50] = u0;
                sm.xyzp[c][1][p + 50] = u1;
                sm.xyzp[c][2][p + 50] = u2;
                sm.xyzp[c][3][p + 50] = u3;
            }
        }
        __syncthreads();

        // ---- combine partials -------------------------------------------
        if (tid < MDIM) {
            const float sc = 1.0f / (float)NNEI;
            float x0 = 0.f, x1 = 0.f, x2 = 0.f, x3 = 0.f;
            #pragma unroll
            for (int cc = 0; cc < 6; cc++) {
                x0 += sm.xyzp[cc][0][tid];
                x1 += sm.xyzp[cc][1][tid];
                x2 += sm.xyzp[cc][2][tid];
                x3 += sm.xyzp[cc][3][tid];
            }
            sm.xyz[0][tid] = x0 * sc;
            sm.xyz[1][tid] = x1 * sc;
            sm.xyz[2][tid] = x2 * sc;
            sm.xyz[3][tid] = x3 * sc;
        }
        __syncthreads();

        // ---- epilogue Gram product: 400 items over 320 threads ----------
        for (int item = tid; item < 400; item += NTHREADS) {
            const int mo = item % 100;
            const int a4 = (item / 100) * 4;
            float y0 = sm.xyz[0][mo], y1 = sm.xyz[1][mo];
            float y2 = sm.xyz[2][mo], y3 = sm.xyz[3][mo];
            float4 v;
            v.x = y0 * sm.xyz[0][a4 + 0] + y1 * sm.xyz[1][a4 + 0]
                + y2 * sm.xyz[2][a4 + 0] + y3 * sm.xyz[3][a4 + 0];
            v.y = y0 * sm.xyz[0][a4 + 1] + y1 * sm.xyz[1][a4 + 1]
                + y2 * sm.xyz[2][a4 + 1] + y3 * sm.xyz[3][a4 + 1];
            v.z = y0 * sm.xyz[0][a4 + 2] + y1 * sm.xyz[1][a4 + 2]
                + y2 * sm.xyz[2][a4 + 2] + y3 * sm.xyz[3][a4 + 2];
            v.w = y0 * sm.xyz[0][a4 + 3] + y1 * sm.xyz[1][a4 + 3]
                + y2 * sm.xyz[2][a4 + 3] + y3 * sm.xyz[3][a4 + 3];
            *(float4*)(out + (long long)row * (MDIM * AXIS) + mo * AXIS + a4) = v;
        }
        __syncthreads();
    }
}

extern "C" void kernel_launch(void* const* d_in, const int* in_sizes, int n_in,
                              void* d_out, int out_size)
{
    const void*  nlist = d_in[0];
    const float* coord = (const float*)d_in[1];
    const void*  atype = d_in[2];
    const float* mean  = (const float*)d_in[3];
    const float* stdv  = (const float*)d_in[4];
    const float* w0    = (const float*)d_in[5];
    const float* b0    = (const float*)d_in[6];
    const float* w1    = (const float*)d_in[7];
    const float* b1    = (const float*)d_in[8];
    const float* w2    = (const float*)d_in[9];
    const float* b2    = (const float*)d_in[10];
    float* out = (float*)d_out;

    cudaFuncSetAttribute(desc_kernel,
                         cudaFuncAttributeMaxDynamicSharedMemorySize,
                         (int)sizeof(SM));

    probe_kernel<<<1, 32>>>((const unsigned*)nlist, (const unsigned*)atype);
    desc_kernel<<<GRID, NTHREADS, sizeof(SM)>>>(
        nlist, coord, atype, mean, stdv, w0, b0, w1, b1, w2, b2, out);
}

// round 11
// speedup vs baseline: 1.8533x; 1.8533x over previous
#include <cuda_runtime.h>
#include <cstdint>

// Problem constants (DescrptSeA)
#define NF      2
#define NLOC    4096
#define NALL    4608
#define NROW    (NF * NLOC)
#define NNEI    138
#define SEC1    46      // type-0 neighbors: [0,46), type-1: [46,138)
#define MDIM    100
#define AXIS    16
#define NTHREADS 320
#define GRID    296     // 2 CTAs per SM x 148 SMs
#define NP      144     // padded neighbor rows: 0-45 t0, 46-47 pad, 48-139 t1, 140-143 pad

typedef unsigned long long ull;

// ---------------------------------------------------------------------------
// dtype probe: reference declares int64 indices, but JAX may emit int32.
// ---------------------------------------------------------------------------
__device__ int g_is64[2];

__global__ void probe_kernel(const unsigned* __restrict__ nlist_w,
                             const unsigned* __restrict__ atype_w) {
    if (threadIdx.x == 0 && blockIdx.x == 0) {
        int nz = 0;
        for (int p = 0; p < 512; p++) nz += (nlist_w[2 * p + 1] != 0u);
        g_is64[0] = (nz == 0) ? 1 : 0;
        nz = 0;
        for (int p = 0; p < 512; p++) nz += (atype_w[2 * p + 1] != 0u);
        g_is64[1] = (nz == 0) ? 1 : 0;
    }
}

__device__ __forceinline__ float tanh_ap(float x) {
    float y;
    asm("tanh.approx.f32 %0, %1;" : "=f"(y) : "f"(x));
    return y;
}

// ---- packed f32x2 helpers --------------------------------------------------
__device__ __forceinline__ ull pack2(float lo, float hi) {
    ull r;
    asm("mov.b64 %0, {%1, %2};" : "=l"(r) : "f"(lo), "f"(hi));
    return r;
}
__device__ __forceinline__ ull ffma2(ull a, ull b, ull c) {
    ull d;
    asm("fma.rn.f32x2 %0, %1, %2, %3;" : "=l"(d) : "l"(a), "l"(b), "l"(c));
    return d;
}
__device__ __forceinline__ ull fadd2(ull a, ull b) {
    ull d;
    asm("add.rn.f32x2 %0, %1, %2;" : "=l"(d) : "l"(a), "l"(b));
    return d;
}
__device__ __forceinline__ float hsum2(ull a) {
    float lo, hi;
    asm("mov.b64 {%0, %1}, %2;" : "=f"(lo), "=f"(hi) : "l"(a));
    return lo + hi;
}

__device__ __forceinline__ long long load_idx(const void* p, long long i, int is64) {
    if (is64) return ((const long long*)p)[i];
    return (long long)((const int*)p)[i];
}

struct SM {
    alignas(16) float envp[NP][4];       // padded env rows (pads = 0)
    alignas(16) float h1p[NP][52];       // padded h1 rows (pads = 0)
    alignas(16) float h0[NNEI][28];      // 25 + zero pad
    alignas(16) float w1T[2][50][28];    // [t][k][j], j>=25 -> 0
    alignas(16) float w0s[2][25];
    float b0s[2][25];
    float b2s[2][100];
    alignas(16) ull   w2p[2][25][100];   // packed over k: w2p[t][q][m] = (w2[2q][m], w2[2q+1][m])
    alignas(16) float xyzq[6][4][MDIM];  // stage-2 partials per slot
    alignas(16) float xyz[4][MDIM];
};

__global__ __launch_bounds__(NTHREADS, 2)
void desc_kernel(const void* __restrict__ nlist_,
                 const float* __restrict__ coord,
                 const void* __restrict__ atype_,
                 const float* __restrict__ mean,
                 const float* __restrict__ stdv,
                 const float* __restrict__ w0,
                 const float* __restrict__ b0,
                 const float* __restrict__ w1,
                 const float* __restrict__ b1,
                 const float* __restrict__ w2,
                 const float* __restrict__ b2,
                 float* __restrict__ out)
{
    extern __shared__ unsigned char smem_raw[];
    SM& sm = *reinterpret_cast<SM*>(smem_raw);

    const int tid = threadIdx.x;
    const int is64n = g_is64[0];
    const int is64a = g_is64[1];

    // ---- one-time smem staging ------------------------------------------
    for (int x = tid; x < 50; x += NTHREADS) {
        int t = x / 25, j = x % 25;
        sm.w0s[t][j] = w0[x];
        sm.b0s[t][j] = b0[x];
    }
    for (int x = tid; x < 2 * 50 * 28; x += NTHREADS) {
        int t = x / (50 * 28);
        int r = x - t * 50 * 28;
        int k = r / 28, j = r - k * 28;
        sm.w1T[t][k][j] = (j < 25) ? w1[t * 1250 + j * 50 + k] : 0.0f;
    }
    for (int x = tid; x < 200; x += NTHREADS) sm.b2s[x / 100][x % 100] = b2[x];
    // packed w2: w2p[t][q][m] = (w2[t][2q][m], w2[t][2q+1][m])
    for (int x = tid; x < 5000; x += NTHREADS) {
        int t = x / 2500;
        int r = x - t * 2500;
        int q = r / 100, mI = r - q * 100;
        sm.w2p[t][q][mI] = pack2(w2[t * 5000 + q * 200 + mI],
                                 w2[t * 5000 + q * 200 + 100 + mI]);
    }
    // zero padded arrays once (pad rows stay zero forever)
    for (int x = tid; x < NP * 52; x += NTHREADS) ((float*)sm.h1p)[x] = 0.0f;
    for (int x = tid; x < NP * 4;  x += NTHREADS) ((float*)sm.envp)[x] = 0.0f;

    // ---- stage-2 roles: 50 col-pairs x 6 slots; 6 type-pure tiles each ---
    const bool s2act = (tid < 300);
    const int tt2 = s2act ? tid : 299;
    const int mg   = tt2 % 50;            // column pair id
    const int slot = tt2 / 50;            // 0..5
    const int m0   = 2 * mg;              // columns m0, m0+1 (never straddle 50)
    const int mm0  = (m0 < 50) ? m0 : m0 - 50;

    // ---- stage h1 roles: 6 segments x 50 k, 23 neighbors each ------------
    const int kh  = tt2 % 50;
    const int seg = tt2 / 50;             // 0..5
    const int th1  = (seg < 2) ? 0 : 1;
    const int hbeg = seg * 23;
    const int hoff = (seg >= 2) ? 2 : 0;  // padded-row offset (uniform per thread)
    const float b1k = b1[th1 * 50 + kh];
    const int km = (kh < 25) ? kh : kh - 25;

    __syncthreads();

    // =====================  persistent row loop  ==========================
    for (int row = blockIdx.x; row < NROW; row += GRID) {
        const int f  = row >> 12;
        const int li = row & (NLOC - 1);

        // ---- stage 1: env matrix (into padded rows) ---------------------
        const long long ci = (long long)f * NALL + li;
        if (tid < NNEI) {
            const int s0 = tid;
            const int sr = s0 + ((s0 >= SEC1) ? 2 : 0);
            const float cx = coord[ci * 3 + 0];
            const float cy = coord[ci * 3 + 1];
            const float cz = coord[ci * 3 + 2];
            const int at = (int)load_idx(atype_, ci, is64a);
            long long nb = load_idx(nlist_, (long long)row * NNEI + s0, is64n);
            bool valid = (nb >= 0);
            long long j = valid ? nb : 0;
            const float* cp = coord + ((long long)f * NALL + j) * 3;
            float dx = cp[0] - cx, dy = cp[1] - cy, dz = cp[2] - cz;
            float r = sqrtf(dx * dx + dy * dy + dz * dz);
            float uu = (r - 0.5f) * (1.0f / 5.5f);
            float vv = uu * uu * uu * (uu * (-6.0f * uu + 15.0f) - 10.0f) + 1.0f;
            float w = (r < 0.5f) ? 1.0f : ((r >= 6.0f) ? 0.0f : vv);
            if (!valid) w = 0.0f;
            float inv = 1.0f / (r + 0.01f);
            float a0 = inv * w;
            float aw = inv * inv * w;
            int base = (at * NNEI + s0) * 4;
            sm.envp[sr][0] = (a0      - mean[base + 0]) / stdv[base + 0];
            sm.envp[sr][1] = (dx * aw - mean[base + 1]) / stdv[base + 1];
            sm.envp[sr][2] = (dy * aw - mean[base + 2]) / stdv[base + 2];
            sm.envp[sr][3] = (dz * aw - mean[base + 3]) / stdv[base + 3];
        }
        __syncthreads();

        // ---- stage h0: 138 x 25 (+ zero pads to 28) ---------------------
        for (int x = tid; x < NNEI * 28; x += NTHREADS) {
            int s0 = x / 28, j = x - s0 * 28;
            int t = (s0 >= SEC1);
            int sr = s0 + ((s0 >= SEC1) ? 2 : 0);
            sm.h0[s0][j] = (j < 25)
                ? tanh_ap(sm.envp[sr][0] * sm.w0s[t][j] + sm.b0s[t][j])
                : 0.0f;
        }
        __syncthreads();

        // ---- stage h1: one k per thread, wk hoisted per row -------------
        if (tid < 300) {
            ulonglong2 wk[7];
            const ulonglong2* w1p = (const ulonglong2*)&sm.w1T[th1][kh][0];
            #pragma unroll
            for (int v = 0; v < 7; v++) wk[v] = w1p[v];
            for (int s0 = hbeg; s0 < hbeg + 23; s0++) {
                const ulonglong2* h0p = (const ulonglong2*)&sm.h0[s0][0];
                ull a0 = 0ull, a1 = 0ull;
                #pragma unroll
                for (int v = 0; v < 7; v++) {
                    ulonglong2 h = h0p[v];
                    a0 = ffma2(h.x, wk[v].x, a0);
                    a1 = ffma2(h.y, wk[v].y, a1);
                }
                float acc = hsum2(fadd2(a0, a1)) + b1k;
                sm.h1p[s0 + hoff][kh] = tanh_ap(acc) + sm.h0[s0][km];
            }
        }
        __syncthreads();

        // ---- stage 2: GEMM-tiled, 4 neighbors x 2 columns per tile ------
        // 6 tiles per thread, all type-pure (t0 = tiles 0-1, t1 = tiles 2-5).
        // Padded rows have env=0 -> contribute nothing.
        {
            ull x01a = 0ull, x23a = 0ull;   // xyz partials, column m0
            ull x01b = 0ull, x23b = 0ull;   // xyz partials, column m0+1
            #pragma unroll 1
            for (int ti = 0; ti < 6; ti++) {
                const int t = (ti < 2) ? 0 : 1;
                const int rbase = 4 * (slot + 6 * ti);
                const ull* w2row = &sm.w2p[t][0][m0];
                ull acc[4][2];
                #pragma unroll
                for (int n = 0; n < 4; n++) { acc[n][0] = 0ull; acc[n][1] = 0ull; }

                #pragma unroll
                for (int q0 = 0; q0 < 24; q0 += 2) {
                    ulonglong2 w2a = *(const ulonglong2*)(w2row + q0 * 100);
                    ulonglong2 w2b = *(const ulonglong2*)(w2row + (q0 + 1) * 100);
                    #pragma unroll
                    for (int n = 0; n < 4; n++) {
                        ulonglong2 h = *(const ulonglong2*)&sm.h1p[rbase + n][2 * q0];
                        acc[n][0] = ffma2(h.x, w2a.x, acc[n][0]);
                        acc[n][1] = ffma2(h.x, w2a.y, acc[n][1]);
                        acc[n][0] = ffma2(h.y, w2b.x, acc[n][0]);
                        acc[n][1] = ffma2(h.y, w2b.y, acc[n][1]);
                    }
                }
                {   // k tail: q = 24 (cols 48,49)
                    ulonglong2 w2t = *(const ulonglong2*)(w2row + 24 * 100);
                    #pragma unroll
                    for (int n = 0; n < 4; n++) {
                        ull h = *(const ull*)&sm.h1p[rbase + n][48];
                        acc[n][0] = ffma2(h, w2t.x, acc[n][0]);
                        acc[n][1] = ffma2(h, w2t.y, acc[n][1]);
                    }
                }
                // tile epilogue: tanh + residual + env accumulate
                const float b2a = sm.b2s[t][m0];
                const float b2b = sm.b2s[t][m0 + 1];
                #pragma unroll
                for (int n = 0; n < 4; n++) {
                    const int rw = rbase + n;
                    float g0 = tanh_ap(hsum2(acc[n][0]) + b2a);
                    float g1 = tanh_ap(hsum2(acc[n][1]) + b2b);
                    float r0, r1;
                    {
                        ull rr = *(const ull*)&sm.h1p[rw][mm0];
                        asm("mov.b64 {%0, %1}, %2;" : "=f"(r0), "=f"(r1) : "l"(rr));
                    }
                    g0 += r0;
                    g1 += r1;
                    ulonglong2 ev = *(const ulonglong2*)&sm.envp[rw][0];
                    ull g02 = pack2(g0, g0);
                    ull g12 = pack2(g1, g1);
                    x01a = ffma2(ev.x, g02, x01a);
                    x23a = ffma2(ev.y, g02, x23a);
                    x01b = ffma2(ev.x, g12, x01b);
                    x23b = ffma2(ev.y, g12, x23b);
                }
            }
            if (s2act) {
                float u0, u1, u2, u3;
                asm("mov.b64 {%0, %1}, %2;" : "=f"(u0), "=f"(u1) : "l"(x01a));
                asm("mov.b64 {%0, %1}, %2;" : "=f"(u2), "=f"(u3) : "l"(x23a));
                sm.xyzq[slot][0][m0] = u0;
                sm.xyzq[slot][1][m0] = u1;
                sm.xyzq[slot][2][m0] = u2;
                sm.xyzq[slot][3][m0] = u3;
                asm("mov.b64 {%0, %1}, %2;" : "=f"(u0), "=f"(u1) : "l"(x01b));
                asm("mov.b64 {%0, %1}, %2;" : "=f"(u2), "=f"(u3) : "l"(x23b));
                sm.xyzq[slot][0][m0 + 1] = u0;
                sm.xyzq[slot][1][m0 + 1] = u1;
                sm.xyzq[slot][2][m0 + 1] = u2;
                sm.xyzq[slot][3][m0 + 1] = u3;
            }
        }
        __syncthreads();

        // ---- combine partials -------------------------------------------
        if (tid < MDIM) {
            const float sc = 1.0f / (float)NNEI;
            float x0 = 0.f, x1 = 0.f, x2 = 0.f, x3 = 0.f;
            #pragma unroll
            for (int ss = 0; ss < 6; ss++) {
                x0 += sm.xyzq[ss][0][tid];
                x1 += sm.xyzq[ss][1][tid];
                x2 += sm.xyzq[ss][2][tid];
                x3 += sm.xyzq[ss][3][tid];
            }
            sm.xyz[0][tid] = x0 * sc;
            sm.xyz[1][tid] = x1 * sc;
            sm.xyz[2][tid] = x2 * sc;
            sm.xyz[3][tid] = x3 * sc;
        }
        __syncthreads();

        // ---- epilogue Gram product: 400 items over 320 threads ----------
        for (int item = tid; item < 400; item += NTHREADS) {
            const int mo = item % 100;
            const int a4 = (item / 100) * 4;
            float y0 = sm.xyz[0][mo], y1 = sm.xyz[1][mo];
            float y2 = sm.xyz[2][mo], y3 = sm.xyz[3][mo];
            float4 v;
            v.x = y0 * sm.xyz[0][a4 + 0] + y1 * sm.xyz[1][a4 + 0]
                + y2 * sm.xyz[2][a4 + 0] + y3 * sm.xyz[3][a4 + 0];
            v.y = y0 * sm.xyz[0][a4 + 1] + y1 * sm.xyz[1][a4 + 1]
                + y2 * sm.xyz[2][a4 + 1] + y3 * sm.xyz[3][a4 + 1];
            v.z = y0 * sm.xyz[0][a4 + 2] + y1 * sm.xyz[1][a4 + 2]
                + y2 * sm.xyz[2][a4 + 2] + y3 * sm.xyz[3][a4 + 2];
            v.w = y0 * sm.xyz[0][a4 + 3] + y1 * sm.xyz[1][a4 + 3]
                + y2 * sm.xyz[2][a4 + 3] + y3 * sm.xyz[3][a4 + 3];
            *(float4*)(out + (long long)row * (MDIM * AXIS) + mo * AXIS + a4) = v;
        }
        __syncthreads();
    }
}

extern "C" void kernel_launch(void* const* d_in, const int* in_sizes, int n_in,
                              void* d_out, int out_size)
{
    const void*  nlist = d_in[0];
    const float* coord = (const float*)d_in[1];
    const void*  atype = d_in[2];
    const float* mean  = (const float*)d_in[3];
    const float* stdv  = (const float*)d_in[4];
    const float* w0    = (const float*)d_in[5];
    const float* b0    = (const float*)d_in[6];
    const float* w1    = (const float*)d_in[7];
    const float* b1    = (const float*)d_in[8];
    const float* w2    = (const float*)d_in[9];
    const float* b2    = (const float*)d_in[10];
    float* out = (float*)d_out;

    cudaFuncSetAttribute(desc_kernel,
                         cudaFuncAttributeMaxDynamicSharedMemorySize,
                         (int)sizeof(SM));

    probe_kernel<<<1, 32>>>((const unsigned*)nlist, (const unsigned*)atype);
    desc_kernel<<<GRID, NTHREADS, sizeof(SM)>>>(
        nlist, coord, atype, mean, stdv, w0, b0, w1, b1, w2, b2, out);
}

// round 12
// speedup vs baseline: 2.0354x; 1.0983x over previous
#include <cuda_runtime.h>
#include <cstdint>

// Problem constants (DescrptSeA)
#define NF      2
#define NLOC    4096
#define NALL    4608
#define NROW    (NF * NLOC)
#define NNEI    138
#define SEC1    46      // type-0 neighbors: [0,46), type-1: [46,138)
#define MDIM    100
#define AXIS    16
#define NTHREADS 320
#define GRID    296     // 2 CTAs per SM x 148 SMs
#define NP      144     // padded rows: 0-45 t0, 46-47 pad, 48-139 t1, 140-143 pad

typedef unsigned long long ull;

// ---------------------------------------------------------------------------
// dtype probe: reference declares int64 indices, but JAX may emit int32.
// ---------------------------------------------------------------------------
__device__ int g_is64[2];

__global__ void probe_kernel(const unsigned* __restrict__ nlist_w,
                             const unsigned* __restrict__ atype_w) {
    if (threadIdx.x == 0 && blockIdx.x == 0) {
        int nz = 0;
        for (int p = 0; p < 512; p++) nz += (nlist_w[2 * p + 1] != 0u);
        g_is64[0] = (nz == 0) ? 1 : 0;
        nz = 0;
        for (int p = 0; p < 512; p++) nz += (atype_w[2 * p + 1] != 0u);
        g_is64[1] = (nz == 0) ? 1 : 0;
    }
}

__device__ __forceinline__ float tanh_ap(float x) {
    float y;
    asm("tanh.approx.f32 %0, %1;" : "=f"(y) : "f"(x));
    return y;
}

// ---- packed f32x2 helpers --------------------------------------------------
__device__ __forceinline__ ull pack2(float lo, float hi) {
    ull r;
    asm("mov.b64 %0, {%1, %2};" : "=l"(r) : "f"(lo), "f"(hi));
    return r;
}
__device__ __forceinline__ ull ffma2(ull a, ull b, ull c) {
    ull d;
    asm("fma.rn.f32x2 %0, %1, %2, %3;" : "=l"(d) : "l"(a), "l"(b), "l"(c));
    return d;
}
__device__ __forceinline__ ull fadd2(ull a, ull b) {
    ull d;
    asm("add.rn.f32x2 %0, %1, %2;" : "=l"(d) : "l"(a), "l"(b));
    return d;
}
__device__ __forceinline__ float hsum2(ull a) {
    float lo, hi;
    asm("mov.b64 {%0, %1}, %2;" : "=f"(lo), "=f"(hi) : "l"(a));
    return lo + hi;
}

__device__ __forceinline__ long long load_idx(const void* p, long long i, int is64) {
    if (is64) return ((const long long*)p)[i];
    return (long long)((const int*)p)[i];
}

struct SM {
    alignas(16) float envp[NP][4];       // padded env rows (pads = 0)
    alignas(16) float h1p[NP][52];       // padded h1 rows (pads = 0)
    alignas(16) float h0[NNEI][28];      // 25 + zero pad
    alignas(16) float w1T[2][50][28];    // [t][k][j], j>=25 -> 0
    alignas(16) float w0s[2][25];
    float b0s[2][25];
    float b2s[2][100];
    alignas(16) ull   w2p[2][25][100];   // w2p[t][q][m] = (w2[2q][m], w2[2q+1][m])
    alignas(16) float xyzq[6][4][MDIM];  // stage-2 partials per (slotg,half)
    alignas(16) float xyz[4][MDIM];
};

__global__ __launch_bounds__(NTHREADS, 2)
void desc_kernel(const void* __restrict__ nlist_,
                 const float* __restrict__ coord,
                 const void* __restrict__ atype_,
                 const float* __restrict__ mean,
                 const float* __restrict__ stdv,
                 const float* __restrict__ w0,
                 const float* __restrict__ b0,
                 const float* __restrict__ w1,
                 const float* __restrict__ b1,
                 const float* __restrict__ w2,
                 const float* __restrict__ b2,
                 float* __restrict__ out)
{
    extern __shared__ unsigned char smem_raw[];
    SM& sm = *reinterpret_cast<SM*>(smem_raw);

    const int tid = threadIdx.x;
    const int is64n = g_is64[0];
    const int is64a = g_is64[1];

    // ---- one-time smem staging ------------------------------------------
    for (int x = tid; x < 50; x += NTHREADS) {
        int t = x / 25, j = x % 25;
        sm.w0s[t][j] = w0[x];
        sm.b0s[t][j] = b0[x];
    }
    for (int x = tid; x < 2 * 50 * 28; x += NTHREADS) {
        int t = x / (50 * 28);
        int r = x - t * 50 * 28;
        int k = r / 28, j = r - k * 28;
        sm.w1T[t][k][j] = (j < 25) ? w1[t * 1250 + j * 50 + k] : 0.0f;
    }
    for (int x = tid; x < 200; x += NTHREADS) sm.b2s[x / 100][x % 100] = b2[x];
    // packed w2: w2p[t][q][m] = (w2[t][2q][m], w2[t][2q+1][m])
    for (int x = tid; x < 5000; x += NTHREADS) {
        int t = x / 2500;
        int r = x - t * 2500;
        int q = r / 100, mI = r - q * 100;
        sm.w2p[t][q][mI] = pack2(w2[t * 5000 + q * 200 + mI],
                                 w2[t * 5000 + q * 200 + 100 + mI]);
    }
    // zero padded arrays once (pad rows stay zero forever)
    for (int x = tid; x < NP * 52; x += NTHREADS) ((float*)sm.h1p)[x] = 0.0f;
    for (int x = tid; x < NP * 4;  x += NTHREADS) ((float*)sm.envp)[x] = 0.0f;

    // ---- stage-2 roles: lane pairs share a column pair, split neighbors --
    // half = tid&1; pairId = tid>>1 -> (mg 0..49, slotg 0..2).
    // Tile ti (0..5): rows rbase..rbase+3, rbase = 8*(slotg+3*ti)+4*half.
    // Covers all 36 four-row blocks of 144 rows exactly once; tiles 0-1 are
    // type-0 rows (<48), tiles 2-5 type-1. w2 LDS addresses now shared by
    // lane pairs -> 2 crossbar phases instead of 4.
    const bool s2act = (tid < 300);
    const int tt2 = s2act ? tid : 299;
    const int half   = tt2 & 1;
    const int pairId = tt2 >> 1;          // 0..149
    const int mg     = pairId % 50;       // column-pair id
    const int slotg  = pairId / 50;       // 0..2
    const int m0     = 2 * mg;            // columns m0, m0+1 (never straddle 50)
    const int mm0    = (m0 < 50) ? m0 : m0 - 50;
    const int wslot  = slotg * 2 + half;  // 0..5 partial-buffer index

    // ---- stage h1 roles: 6 segments x 50 k, 23 neighbors each ------------
    const int kh  = tt2 % 50;
    const int seg = tt2 / 50;             // 0..5
    const int th1  = (seg < 2) ? 0 : 1;
    const int hbeg = seg * 23;
    const int hoff = (seg >= 2) ? 2 : 0;  // padded-row offset
    const float b1k = b1[th1 * 50 + kh];
    const int km = (kh < 25) ? kh : kh - 25;

    __syncthreads();

    // =====================  persistent row loop  ==========================
    for (int row = blockIdx.x; row < NROW; row += GRID) {
        const int f  = row >> 12;
        const int li = row & (NLOC - 1);

        // ---- stage 1: env matrix (into padded rows) ---------------------
        const long long ci = (long long)f * NALL + li;
        if (tid < NNEI) {
            const int s0 = tid;
            const int sr = s0 + ((s0 >= SEC1) ? 2 : 0);
            const float cx = coord[ci * 3 + 0];
            const float cy = coord[ci * 3 + 1];
            const float cz = coord[ci * 3 + 2];
            const int at = (int)load_idx(atype_, ci, is64a);
            long long nb = load_idx(nlist_, (long long)row * NNEI + s0, is64n);
            bool valid = (nb >= 0);
            long long j = valid ? nb : 0;
            const float* cp = coord + ((long long)f * NALL + j) * 3;
            float dx = cp[0] - cx, dy = cp[1] - cy, dz = cp[2] - cz;
            float r = sqrtf(dx * dx + dy * dy + dz * dz);
            float uu = (r - 0.5f) * (1.0f / 5.5f);
            float vv = uu * uu * uu * (uu * (-6.0f * uu + 15.0f) - 10.0f) + 1.0f;
            float w = (r < 0.5f) ? 1.0f : ((r >= 6.0f) ? 0.0f : vv);
            if (!valid) w = 0.0f;
            float inv = 1.0f / (r + 0.01f);
            float a0 = inv * w;
            float aw = inv * inv * w;
            int base = (at * NNEI + s0) * 4;
            sm.envp[sr][0] = (a0      - mean[base + 0]) / stdv[base + 0];
            sm.envp[sr][1] = (dx * aw - mean[base + 1]) / stdv[base + 1];
            sm.envp[sr][2] = (dy * aw - mean[base + 2]) / stdv[base + 2];
            sm.envp[sr][3] = (dz * aw - mean[base + 3]) / stdv[base + 3];
        }
        __syncthreads();

        // ---- stage h0: 138 x 25 (+ zero pads to 28) ---------------------
        for (int x = tid; x < NNEI * 28; x += NTHREADS) {
            int s0 = x / 28, j = x - s0 * 28;
            int t = (s0 >= SEC1);
            int sr = s0 + ((s0 >= SEC1) ? 2 : 0);
            sm.h0[s0][j] = (j < 25)
                ? tanh_ap(sm.envp[sr][0] * sm.w0s[t][j] + sm.b0s[t][j])
                : 0.0f;
        }
        __syncthreads();

        // ---- stage h1: one k per thread, wk hoisted per row -------------
        if (tid < 300) {
            ulonglong2 wk[7];
            const ulonglong2* w1p = (const ulonglong2*)&sm.w1T[th1][kh][0];
            #pragma unroll
            for (int v = 0; v < 7; v++) wk[v] = w1p[v];
            for (int s0 = hbeg; s0 < hbeg + 23; s0++) {
                const ulonglong2* h0p = (const ulonglong2*)&sm.h0[s0][0];
                ull a0 = 0ull, a1 = 0ull;
                #pragma unroll
                for (int v = 0; v < 7; v++) {
                    ulonglong2 h = h0p[v];
                    a0 = ffma2(h.x, wk[v].x, a0);
                    a1 = ffma2(h.y, wk[v].y, a1);
                }
                float acc = hsum2(fadd2(a0, a1)) + b1k;
                sm.h1p[s0 + hoff][kh] = tanh_ap(acc) + sm.h0[s0][km];
            }
        }
        __syncthreads();

        // ---- stage 2: GEMM-tiled, 4 neighbors x 2 columns per thread ----
        {
            ull x01a = 0ull, x23a = 0ull;   // xyz partials, column m0
            ull x01b = 0ull, x23b = 0ull;   // xyz partials, column m0+1
            #pragma unroll 1
            for (int ti = 0; ti < 6; ti++) {
                const int t = (ti < 2) ? 0 : 1;
                const int rbase = 8 * (slotg + 3 * ti) + 4 * half;
                const ull* w2row = &sm.w2p[t][0][m0];
                ull acc[4][2];
                #pragma unroll
                for (int n = 0; n < 4; n++) { acc[n][0] = 0ull; acc[n][1] = 0ull; }

                #pragma unroll
                for (int q0 = 0; q0 < 24; q0 += 2) {
                    ulonglong2 w2a = *(const ulonglong2*)(w2row + q0 * 100);
                    ulonglong2 w2b = *(const ulonglong2*)(w2row + (q0 + 1) * 100);
                    #pragma unroll
                    for (int n = 0; n < 4; n++) {
                        ulonglong2 h = *(const ulonglong2*)&sm.h1p[rbase + n][2 * q0];
                        acc[n][0] = ffma2(h.x, w2a.x, acc[n][0]);
                        acc[n][1] = ffma2(h.x, w2a.y, acc[n][1]);
                        acc[n][0] = ffma2(h.y, w2b.x, acc[n][0]);
                        acc[n][1] = ffma2(h.y, w2b.y, acc[n][1]);
                    }
                }
                {   // k tail: q = 24 (cols 48,49)
                    ulonglong2 w2t = *(const ulonglong2*)(w2row + 24 * 100);
                    #pragma unroll
                    for (int n = 0; n < 4; n++) {
                        ull h = *(const ull*)&sm.h1p[rbase + n][48];
                        acc[n][0] = ffma2(h, w2t.x, acc[n][0]);
                        acc[n][1] = ffma2(h, w2t.y, acc[n][1]);
                    }
                }
                // tile epilogue: tanh + residual + env accumulate
                const float b2a = sm.b2s[t][m0];
                const float b2b = sm.b2s[t][m0 + 1];
                #pragma unroll
                for (int n = 0; n < 4; n++) {
                    const int rw = rbase + n;
                    float g0 = tanh_ap(hsum2(acc[n][0]) + b2a);
                    float g1 = tanh_ap(hsum2(acc[n][1]) + b2b);
                    float r0, r1;
                    {
                        ull rr = *(const ull*)&sm.h1p[rw][mm0];
                        asm("mov.b64 {%0, %1}, %2;" : "=f"(r0), "=f"(r1) : "l"(rr));
                    }
                    g0 += r0;
                    g1 += r1;
                    ulonglong2 ev = *(const ulonglong2*)&sm.envp[rw][0];
                    ull g02 = pack2(g0, g0);
                    ull g12 = pack2(g1, g1);
                    x01a = ffma2(ev.x, g02, x01a);
                    x23a = ffma2(ev.y, g02, x23a);
                    x01b = ffma2(ev.x, g12, x01b);
                    x23b = ffma2(ev.y, g12, x23b);
                }
            }
            if (s2act) {
                float u0, u1, u2, u3;
                asm("mov.b64 {%0, %1}, %2;" : "=f"(u0), "=f"(u1) : "l"(x01a));
                asm("mov.b64 {%0, %1}, %2;" : "=f"(u2), "=f"(u3) : "l"(x23a));
                sm.xyzq[wslot][0][m0] = u0;
                sm.xyzq[wslot][1][m0] = u1;
                sm.xyzq[wslot][2][m0] = u2;
                sm.xyzq[wslot][3][m0] = u3;
                asm("mov.b64 {%0, %1}, %2;" : "=f"(u0), "=f"(u1) : "l"(x01b));
                asm("mov.b64 {%0, %1}, %2;" : "=f"(u2), "=f"(u3) : "l"(x23b));
                sm.xyzq[wslot][0][m0 + 1] = u0;
                sm.xyzq[wslot][1][m0 + 1] = u1;
                sm.xyzq[wslot][2][m0 + 1] = u2;
                sm.xyzq[wslot][3][m0 + 1] = u3;
            }
        }
        __syncthreads();

        // ---- combine partials -------------------------------------------
        if (tid < MDIM) {
            const float sc = 1.0f / (float)NNEI;
            float x0 = 0.f, x1 = 0.f, x2 = 0.f, x3 = 0.f;
            #pragma unroll
            for (int ss = 0; ss < 6; ss++) {
                x0 += sm.xyzq[ss][0][tid];
                x1 += sm.xyzq[ss][1][tid];
                x2 += sm.xyzq[ss][2][tid];
                x3 += sm.xyzq[ss][3][tid];
            }
            sm.xyz[0][tid] = x0 * sc;
            sm.xyz[1][tid] = x1 * sc;
            sm.xyz[2][tid] = x2 * sc;
            sm.xyz[3][tid] = x3 * sc;
        }
        __syncthreads();

        // ---- epilogue Gram product: 400 items over 320 threads ----------
        for (int item = tid; item < 400; item += NTHREADS) {
            const int mo = item % 100;
            const int a4 = (item / 100) * 4;
            float y0 = sm.xyz[0][mo], y1 = sm.xyz[1][mo];
            float y2 = sm.xyz[2][mo], y3 = sm.xyz[3][mo];
            float4 v;
            v.x = y0 * sm.xyz[0][a4 + 0] + y1 * sm.xyz[1][a4 + 0]
                + y2 * sm.xyz[2][a4 + 0] + y3 * sm.xyz[3][a4 + 0];
            v.y = y0 * sm.xyz[0][a4 + 1] + y1 * sm.xyz[1][a4 + 1]
                + y2 * sm.xyz[2][a4 + 1] + y3 * sm.xyz[3][a4 + 1];
            v.z = y0 * sm.xyz[0][a4 + 2] + y1 * sm.xyz[1][a4 + 2]
                + y2 * sm.xyz[2][a4 + 2] + y3 * sm.xyz[3][a4 + 2];
            v.w = y0 * sm.xyz[0][a4 + 3] + y1 * sm.xyz[1][a4 + 3]
                + y2 * sm.xyz[2][a4 + 3] + y3 * sm.xyz[3][a4 + 3];
            *(float4*)(out + (long long)row * (MDIM * AXIS) + mo * AXIS + a4) = v;
        }
        __syncthreads();
    }
}

extern "C" void kernel_launch(void* const* d_in, const int* in_sizes, int n_in,
                              void* d_out, int out_size)
{
    const void*  nlist = d_in[0];
    const float* coord = (const float*)d_in[1];
    const void*  atype = d_in[2];
    const float* mean  = (const float*)d_in[3];
    const float* stdv  = (const float*)d_in[4];
    const float* w0    = (const float*)d_in[5];
    const float* b0    = (const float*)d_in[6];
    const float* w1    = (const float*)d_in[7];
    const float* b1    = (const float*)d_in[8];
    const float* w2    = (const float*)d_in[9];
    const float* b2    = (const float*)d_in[10];
    float* out = (float*)d_out;

    cudaFuncSetAttribute(desc_kernel,
                         cudaFuncAttributeMaxDynamicSharedMemorySize,
                         (int)sizeof(SM));

    probe_kernel<<<1, 32>>>((const unsigned*)nlist, (const unsigned*)atype);
    desc_kernel<<<GRID, NTHREADS, sizeof(SM)>>>(
        nlist, coord, atype, mean, stdv, w0, b0, w1, b1, w2, b2, out);
}

// round 15
// speedup vs baseline: 2.0839x; 1.0238x over previous
// R15 == R13/R14 kernel, resubmitted verbatim after two broker-side
// "GB300 container failed twice" infra failures. 6-row x 2-col stage-2 tiles.
#include <cuda_runtime.h>
#include <cstdint>

// Problem constants (DescrptSeA)
#define NF      2
#define NLOC    4096
#define NALL    4608
#define NROW    (NF * NLOC)
#define NNEI    138
#define SEC1    46      // type-0 neighbors: [0,46), type-1: [46,138)
#define MDIM    100
#define AXIS    16
#define NTHREADS 320
#define GRID    296     // 2 CTAs per SM x 148 SMs
#define NP      144     // padded rows: 0-45 t0, 46-47 pad, 48-139 t1, 140-143 pad

typedef unsigned long long ull;

// ---------------------------------------------------------------------------
// dtype probe: reference declares int64 indices, but JAX may emit int32.
// ---------------------------------------------------------------------------
__device__ int g_is64[2];

__global__ void probe_kernel(const unsigned* __restrict__ nlist_w,
                             const unsigned* __restrict__ atype_w) {
    if (threadIdx.x == 0 && blockIdx.x == 0) {
        int nz = 0;
        for (int p = 0; p < 512; p++) nz += (nlist_w[2 * p + 1] != 0u);
        g_is64[0] = (nz == 0) ? 1 : 0;
        nz = 0;
        for (int p = 0; p < 512; p++) nz += (atype_w[2 * p + 1] != 0u);
        g_is64[1] = (nz == 0) ? 1 : 0;
    }
}

__device__ __forceinline__ float tanh_ap(float x) {
    float y;
    asm("tanh.approx.f32 %0, %1;" : "=f"(y) : "f"(x));
    return y;
}

// ---- packed f32x2 helpers --------------------------------------------------
__device__ __forceinline__ ull pack2(float lo, float hi) {
    ull r;
    asm("mov.b64 %0, {%1, %2};" : "=l"(r) : "f"(lo), "f"(hi));
    return r;
}
__device__ __forceinline__ ull ffma2(ull a, ull b, ull c) {
    ull d;
    asm("fma.rn.f32x2 %0, %1, %2, %3;" : "=l"(d) : "l"(a), "l"(b), "l"(c));
    return d;
}
__device__ __forceinline__ ull fadd2(ull a, ull b) {
    ull d;
    asm("add.rn.f32x2 %0, %1, %2;" : "=l"(d) : "l"(a), "l"(b));
    return d;
}
__device__ __forceinline__ float hsum2(ull a) {
    float lo, hi;
    asm("mov.b64 {%0, %1}, %2;" : "=f"(lo), "=f"(hi) : "l"(a));
    return lo + hi;
}

__device__ __forceinline__ long long load_idx(const void* p, long long i, int is64) {
    if (is64) return ((const long long*)p)[i];
    return (long long)((const int*)p)[i];
}

struct SM {
    alignas(16) float envp[NP][4];       // padded env rows (pads = 0)
    alignas(16) float h1p[NP][52];       // padded h1 rows (pads = 0)
    alignas(16) float h0[NNEI][28];      // 25 + zero pad
    alignas(16) float w1T[2][50][28];    // [t][k][j], j>=25 -> 0
    alignas(16) float w0s[2][25];
    float b0s[2][25];
    float b2s[2][100];
    alignas(16) ull   w2p[2][25][100];   // w2p[t][q][m] = (w2[2q][m], w2[2q+1][m])
    alignas(16) float xyzq[6][4][MDIM];  // stage-2 partials per (slotg,half)
    alignas(16) float xyz[4][MDIM];
};

__global__ __launch_bounds__(NTHREADS, 2)
void desc_kernel(const void* __restrict__ nlist_,
                 const float* __restrict__ coord,
                 const void* __restrict__ atype_,
                 const float* __restrict__ mean,
                 const float* __restrict__ stdv,
                 const float* __restrict__ w0,
                 const float* __restrict__ b0,
                 const float* __restrict__ w1,
                 const float* __restrict__ b1,
                 const float* __restrict__ w2,
                 const float* __restrict__ b2,
                 float* __restrict__ out)
{
    extern __shared__ unsigned char smem_raw[];
    SM& sm = *reinterpret_cast<SM*>(smem_raw);

    const int tid = threadIdx.x;
    const int is64n = g_is64[0];
    const int is64a = g_is64[1];

    // ---- one-time smem staging ------------------------------------------
    for (int x = tid; x < 50; x += NTHREADS) {
        int t = x / 25, j = x % 25;
        sm.w0s[t][j] = w0[x];
        sm.b0s[t][j] = b0[x];
    }
    for (int x = tid; x < 2 * 50 * 28; x += NTHREADS) {
        int t = x / (50 * 28);
        int r = x - t * 50 * 28;
        int k = r / 28, j = r - k * 28;
        sm.w1T[t][k][j] = (j < 25) ? w1[t * 1250 + j * 50 + k] : 0.0f;
    }
    for (int x = tid; x < 200; x += NTHREADS) sm.b2s[x / 100][x % 100] = b2[x];
    // packed w2: w2p[t][q][m] = (w2[t][2q][m], w2[t][2q+1][m])
    for (int x = tid; x < 5000; x += NTHREADS) {
        int t = x / 2500;
        int r = x - t * 2500;
        int q = r / 100, mI = r - q * 100;
        sm.w2p[t][q][mI] = pack2(w2[t * 5000 + q * 200 + mI],
                                 w2[t * 5000 + q * 200 + 100 + mI]);
    }
    // zero padded arrays once (pad rows stay zero forever)
    for (int x = tid; x < NP * 52; x += NTHREADS) ((float*)sm.h1p)[x] = 0.0f;
    for (int x = tid; x < NP * 4;  x += NTHREADS) ((float*)sm.envp)[x] = 0.0f;

    // ---- stage-2 roles: lane pairs share a column pair; 6-row tiles ------
    // half = tid&1; pairId = tid>>1 -> (mg 0..49, slotg 0..2).
    // s6 = 2*slotg+half (0..5). Tile index tIdx = s6 + 6*ti, ti = 0..3.
    // Rows rbase = 6*tIdx. Type boundary at row 48 = tile 8 (exact), so
    // tile type t = (tIdx >= 8), uniform per (thread, ti).
    const bool s2act = (tid < 300);
    const int tt2 = s2act ? tid : 299;
    const int half   = tt2 & 1;
    const int pairId = tt2 >> 1;          // 0..149
    const int mg     = pairId % 50;       // column-pair id
    const int slotg  = pairId / 50;       // 0..2
    const int m0     = 2 * mg;            // columns m0, m0+1
    const int mm0    = (m0 < 50) ? m0 : m0 - 50;
    const int s6     = slotg * 2 + half;  // 0..5 (also partial-buffer index)

    // ---- stage h1 roles: 6 segments x 50 k, 23 neighbors each ------------
    const int kh  = tt2 % 50;
    const int seg = tt2 / 50;             // 0..5
    const int th1  = (seg < 2) ? 0 : 1;
    const int hbeg = seg * 23;
    const int hoff = (seg >= 2) ? 2 : 0;  // padded-row offset
    const float b1k = b1[th1 * 50 + kh];
    const int km = (kh < 25) ? kh : kh - 25;

    // ---- hoisted epilogue indices (row-invariant) -------------------------
    const int epi_m0 = tid % 100;
    const int epi_a0 = (tid / 100) * 4;        // item = tid       (tid < 320)
    const int epi_m1 = (tid + 320) % 100;      // item = tid + 320 (tid < 80)
    const int epi_a1 = ((tid + 320) / 100) * 4;

    __syncthreads();

    // =====================  persistent row loop  ==========================
    for (int row = blockIdx.x; row < NROW; row += GRID) {
        const int f  = row >> 12;
        const int li = row & (NLOC - 1);

        // ---- stage 1: env matrix (into padded rows) ---------------------
        const long long ci = (long long)f * NALL + li;
        if (tid < NNEI) {
            const int s0 = tid;
            const int sr = s0 + ((s0 >= SEC1) ? 2 : 0);
            const float cx = coord[ci * 3 + 0];
            const float cy = coord[ci * 3 + 1];
            const float cz = coord[ci * 3 + 2];
            const int at = (int)load_idx(atype_, ci, is64a);
            long long nb = load_idx(nlist_, (long long)row * NNEI + s0, is64n);
            bool valid = (nb >= 0);
            long long j = valid ? nb : 0;
            const float* cp = coord + ((long long)f * NALL + j) * 3;
            float dx = cp[0] - cx, dy = cp[1] - cy, dz = cp[2] - cz;
            float r = sqrtf(dx * dx + dy * dy + dz * dz);
            float uu = (r - 0.5f) * (1.0f / 5.5f);
            float vv = uu * uu * uu * (uu * (-6.0f * uu + 15.0f) - 10.0f) + 1.0f;
            float w = (r < 0.5f) ? 1.0f : ((r >= 6.0f) ? 0.0f : vv);
            if (!valid) w = 0.0f;
            float inv = 1.0f / (r + 0.01f);
            float a0 = inv * w;
            float aw = inv * inv * w;
            int base = (at * NNEI + s0) * 4;
            sm.envp[sr][0] = (a0      - mean[base + 0]) / stdv[base + 0];
            sm.envp[sr][1] = (dx * aw - mean[base + 1]) / stdv[base + 1];
            sm.envp[sr][2] = (dy * aw - mean[base + 2]) / stdv[base + 2];
            sm.envp[sr][3] = (dz * aw - mean[base + 3]) / stdv[base + 3];
        }
        __syncthreads();

        // ---- stage h0: incremental indices, no div/mod in loop ----------
        {
            int s0 = tid / 28;
            int j  = tid - s0 * 28;
            while (s0 < NNEI) {
                int t  = (s0 >= SEC1);
                int sr = s0 + (t ? 2 : 0);
                sm.h0[s0][j] = (j < 25)
                    ? tanh_ap(sm.envp[sr][0] * sm.w0s[t][j] + sm.b0s[t][j])
                    : 0.0f;
                // advance by NTHREADS=320 = 11*28 + 12
                s0 += 11;
                j  += 12;
                if (j >= 28) { j -= 28; s0 += 1; }
            }
        }
        __syncthreads();

        // ---- stage h1: one k per thread, wk hoisted per row -------------
        if (tid < 300) {
            ulonglong2 wk[7];
            const ulonglong2* w1p = (const ulonglong2*)&sm.w1T[th1][kh][0];
            #pragma unroll
            for (int v = 0; v < 7; v++) wk[v] = w1p[v];
            for (int s0 = hbeg; s0 < hbeg + 23; s0++) {
                const ulonglong2* h0p = (const ulonglong2*)&sm.h0[s0][0];
                ull a0 = 0ull, a1 = 0ull;
                #pragma unroll
                for (int v = 0; v < 7; v++) {
                    ulonglong2 h = h0p[v];
                    a0 = ffma2(h.x, wk[v].x, a0);
                    a1 = ffma2(h.y, wk[v].y, a1);
                }
                float acc = hsum2(fadd2(a0, a1)) + b1k;
                sm.h1p[s0 + hoff][kh] = tanh_ap(acc) + sm.h0[s0][km];
            }
        }
        __syncthreads();

        // ---- stage 2: GEMM-tiled, 6 neighbors x 2 columns per thread ----
        {
            ull x01a = 0ull, x23a = 0ull;   // xyz partials, column m0
            ull x01b = 0ull, x23b = 0ull;   // xyz partials, column m0+1
            #pragma unroll 1
            for (int ti = 0; ti < 4; ti++) {
                const int tIdx = s6 + 6 * ti;
                const int t = (tIdx >= 8) ? 1 : 0;
                const int rbase = 6 * tIdx;
                const ull* w2row = &sm.w2p[t][0][m0];
                ull acc[6][2];
                #pragma unroll
                for (int n = 0; n < 6; n++) { acc[n][0] = 0ull; acc[n][1] = 0ull; }

                #pragma unroll
                for (int q0 = 0; q0 < 24; q0 += 2) {
                    ulonglong2 w2a = *(const ulonglong2*)(w2row + q0 * 100);
                    ulonglong2 w2b = *(const ulonglong2*)(w2row + (q0 + 1) * 100);
                    #pragma unroll
                    for (int n = 0; n < 6; n++) {
                        ulonglong2 h = *(const ulonglong2*)&sm.h1p[rbase + n][2 * q0];
                        acc[n][0] = ffma2(h.x, w2a.x, acc[n][0]);
                        acc[n][1] = ffma2(h.x, w2a.y, acc[n][1]);
                        acc[n][0] = ffma2(h.y, w2b.x, acc[n][0]);
                        acc[n][1] = ffma2(h.y, w2b.y, acc[n][1]);
                    }
                }
                {   // k tail: q = 24 (cols 48,49)
                    ulonglong2 w2t = *(const ulonglong2*)(w2row + 24 * 100);
                    #pragma unroll
                    for (int n = 0; n < 6; n++) {
                        ull h = *(const ull*)&sm.h1p[rbase + n][48];
                        acc[n][0] = ffma2(h, w2t.x, acc[n][0]);
                        acc[n][1] = ffma2(h, w2t.y, acc[n][1]);
                    }
                }
                // tile epilogue: tanh + residual + env accumulate
                const float b2a = sm.b2s[t][m0];
                const float b2b = sm.b2s[t][m0 + 1];
                #pragma unroll
                for (int n = 0; n < 6; n++) {
                    const int rw = rbase + n;
                    float g0 = tanh_ap(hsum2(acc[n][0]) + b2a);
                    float g1 = tanh_ap(hsum2(acc[n][1]) + b2b);
                    float r0, r1;
                    {
                        ull rr = *(const ull*)&sm.h1p[rw][mm0];
                        asm("mov.b64 {%0, %1}, %2;" : "=f"(r0), "=f"(r1) : "l"(rr));
                    }
                    g0 += r0;
                    g1 += r1;
                    ulonglong2 ev = *(const ulonglong2*)&sm.envp[rw][0];
                    ull g02 = pack2(g0, g0);
                    ull g12 = pack2(g1, g1);
                    x01a = ffma2(ev.x, g02, x01a);
                    x23a = ffma2(ev.y, g02, x23a);
                    x01b = ffma2(ev.x, g12, x01b);
                    x23b = ffma2(ev.y, g12, x23b);
                }
            }
            if (s2act) {
                float u0, u1, u2, u3;
                asm("mov.b64 {%0, %1}, %2;" : "=f"(u0), "=f"(u1) : "l"(x01a));
                asm("mov.b64 {%0, %1}, %2;" : "=f"(u2), "=f"(u3) : "l"(x23a));
                sm.xyzq[s6][0][m0] = u0;
                sm.xyzq[s6][1][m0] = u1;
                sm.xyzq[s6][2][m0] = u2;
                sm.xyzq[s6][3][m0] = u3;
                asm("mov.b64 {%0, %1}, %2;" : "=f"(u0), "=f"(u1) : "l"(x01b));
                asm("mov.b64 {%0, %1}, %2;" : "=f"(u2), "=f"(u3) : "l"(x23b));
                sm.xyzq[s6][0][m0 + 1] = u0;
                sm.xyzq[s6][1][m0 + 1] = u1;
                sm.xyzq[s6][2][m0 + 1] = u2;
                sm.xyzq[s6][3][m0 + 1] = u3;
            }
        }
        __syncthreads();

        // ---- combine partials -------------------------------------------
        if (tid < MDIM) {
            const float sc = 1.0f / (float)NNEI;
            float x0 = 0.f, x1 = 0.f, x2 = 0.f, x3 = 0.f;
            #pragma unroll
            for (int ss = 0; ss < 6; ss++) {
                x0 += sm.xyzq[ss][0][tid];
                x1 += sm.xyzq[ss][1][tid];
                x2 += sm.xyzq[ss][2][tid];
                x3 += sm.xyzq[ss][3][tid];
            }
            sm.xyz[0][tid] = x0 * sc;
            sm.xyz[1][tid] = x1 * sc;
            sm.xyz[2][tid] = x2 * sc;
            sm.xyz[3][tid] = x3 * sc;
        }
        __syncthreads();

        // ---- epilogue Gram product (indices hoisted) --------------------
        {
            float* ob = out + (long long)row * (MDIM * AXIS);
            {
                const int mo = epi_m0, a4 = epi_a0;
                float y0 = sm.xyz[0][mo], y1 = sm.xyz[1][mo];
                float y2 = sm.xyz[2][mo], y3 = sm.xyz[3][mo];
                float4 v;
                v.x = y0 * sm.xyz[0][a4 + 0] + y1 * sm.xyz[1][a4 + 0]
                    + y2 * sm.xyz[2][a4 + 0] + y3 * sm.xyz[3][a4 + 0];
                v.y = y0 * sm.xyz[0][a4 + 1] + y1 * sm.xyz[1][a4 + 1]
                    + y2 * sm.xyz[2][a4 + 1] + y3 * sm.xyz[3][a4 + 1];
                v.z = y0 * sm.xyz[0][a4 + 2] + y1 * sm.xyz[1][a4 + 2]
                    + y2 * sm.xyz[2][a4 + 2] + y3 * sm.xyz[3][a4 + 2];
                v.w = y0 * sm.xyz[0][a4 + 3] + y1 * sm.xyz[1][a4 + 3]
                    + y2 * sm.xyz[2][a4 + 3] + y3 * sm.xyz[3][a4 + 3];
                *(float4*)(ob + mo * AXIS + a4) = v;
            }
            if (tid < 80) {
                const int mo = epi_m1, a4 = epi_a1;
                float y0 = sm.xyz[0][mo], y1 = sm.xyz[1][mo];
                float y2 = sm.xyz[2][mo], y3 = sm.xyz[3][mo];
                float4 v;
                v.x = y0 * sm.xyz[0][a4 + 0] + y1 * sm.xyz[1][a4 + 0]
                    + y2 * sm.xyz[2][a4 + 0] + y3 * sm.xyz[3][a4 + 0];
                v.y = y0 * sm.xyz[0][a4 + 1] + y1 * sm.xyz[1][a4 + 1]
                    + y2 * sm.xyz[2][a4 + 1] + y3 * sm.xyz[3][a4 + 1];
                v.z = y0 * sm.xyz[0][a4 + 2] + y1 * sm.xyz[1][a4 + 2]
                    + y2 * sm.xyz[2][a4 + 2] + y3 * sm.xyz[3][a4 + 2];
                v.w = y0 * sm.xyz[0][a4 + 3] + y1 * sm.xyz[1][a4 + 3]
                    + y2 * sm.xyz[2][a4 + 3] + y3 * sm.xyz[3][a4 + 3];
                *(float4*)(ob + mo * AXIS + a4) = v;
            }
        }
        __syncthreads();
    }
}

extern "C" void kernel_launch(void* const* d_in, const int* in_sizes, int n_in,
                              void* d_out, int out_size)
{
    const void*  nlist = d_in[0];
    const float* coord = (const float*)d_in[1];
    const void*  atype = d_in[2];
    const float* mean  = (const float*)d_in[3];
    const float* stdv  = (const float*)d_in[4];
    const float* w0    = (const float*)d_in[5];
    const float* b0    = (const float*)d_in[6];
    const float* w1    = (const float*)d_in[7];
    const float* b1    = (const float*)d_in[8];
    const float* w2    = (const float*)d_in[9];
    const float* b2    = (const float*)d_in[10];
    float* out = (float*)d_out;

    cudaFuncSetAttribute(desc_kernel,
                         cudaFuncAttributeMaxDynamicSharedMemorySize,
                         (int)sizeof(SM));

    probe_kernel<<<1, 32>>>((const unsigned*)nlist, (const unsigned*)atype);
    desc_kernel<<<GRID, NTHREADS, sizeof(SM)>>>(
        nlist, coord, atype, mean, stdv, w0, b0, w1, b1, w2, b2, out);
}